// round 3
// baseline (speedup 1.0000x reference)
#include <cuda_runtime.h>
#include <math.h>

// Problem constants
#define BATCH 4
#define CCH   192        // channels
#define NPIX  65536      // H*W
#define HEADS 8
#define CH    24         // channels per head (192/8)

// Gram split-K config
#define SPLIT 32
#define KCH   (NPIX / SPLIT)   // 2048

// ---------------- device scratch (static, no allocation) ----------------
__device__ float g_Spart[BATCH * 9 * SPLIT * 4096]; // per (b,tile,split) 64x64 partials
__device__ float g_S[BATCH * CCH * CCH];            // Gram X X^T per batch
__device__ float g_attn[BATCH * HEADS * CH * CH];   // softmaxed attention
__device__ float g_M[BATCH * CCH * CCH];            // W_out @ blockdiag(attn)
__device__ float g_P[BATCH * CCH * CCH];            // M @ W_v

// =====================================================================
// Kernel 1: partial Gram. grid (SPLIT, 9, BATCH), 256 threads.
// Block computes a 64x64 tile of S over a 2048-long K chunk.
// =====================================================================
__global__ __launch_bounds__(256) void gram_partial(const float* __restrict__ X) {
    const int split = blockIdx.x;
    const int tile  = blockIdx.y;
    const int b     = blockIdx.z;
    const int ti = tile / 3, tj = tile % 3;

    const float* Xb = X + (size_t)b * CCH * NPIX;

    const int t   = threadIdx.x;
    const int lr  = t >> 2;          // 0..63 : row within tile for loads
    const int lk  = (t & 3) * 4;     // 0,4,8,12 : k offset for loads
    const int tx  = t & 15;          // 0..15
    const int ty  = t >> 4;          // 0..15

    __shared__ float As[2][16][68];
    __shared__ float Bs[2][16][68];

    const float* ag = Xb + (size_t)(ti * 64 + lr) * NPIX + split * KCH + lk;
    const float* bg = Xb + (size_t)(tj * 64 + lr) * NPIX + split * KCH + lk;

    // preload tile 0
    float4 av = *(const float4*)ag;
    float4 bv = *(const float4*)bg;
    As[0][lk + 0][lr] = av.x; As[0][lk + 1][lr] = av.y;
    As[0][lk + 2][lr] = av.z; As[0][lk + 3][lr] = av.w;
    Bs[0][lk + 0][lr] = bv.x; Bs[0][lk + 1][lr] = bv.y;
    Bs[0][lk + 2][lr] = bv.z; Bs[0][lk + 3][lr] = bv.w;
    __syncthreads();

    float acc[4][4];
#pragma unroll
    for (int i = 0; i < 4; i++)
#pragma unroll
        for (int j = 0; j < 4; j++) acc[i][j] = 0.f;

    int buf = 0;
    const int NT = KCH / 16;   // 128
#pragma unroll 1
    for (int kt = 0; kt < NT; kt++) {
        float4 an, bn;
        if (kt + 1 < NT) {
            an = *(const float4*)(ag + (kt + 1) * 16);
            bn = *(const float4*)(bg + (kt + 1) * 16);
        }
#pragma unroll
        for (int kk = 0; kk < 16; kk++) {
            float4 a  = *(const float4*)&As[buf][kk][ty * 4];
            float4 bb = *(const float4*)&Bs[buf][kk][tx * 4];
            float ar[4] = {a.x, a.y, a.z, a.w};
            float br[4] = {bb.x, bb.y, bb.z, bb.w};
#pragma unroll
            for (int i = 0; i < 4; i++)
#pragma unroll
                for (int j = 0; j < 4; j++)
                    acc[i][j] = fmaf(ar[i], br[j], acc[i][j]);
        }
        if (kt + 1 < NT) {
            buf ^= 1;
            As[buf][lk + 0][lr] = an.x; As[buf][lk + 1][lr] = an.y;
            As[buf][lk + 2][lr] = an.z; As[buf][lk + 3][lr] = an.w;
            Bs[buf][lk + 0][lr] = bn.x; Bs[buf][lk + 1][lr] = bn.y;
            Bs[buf][lk + 2][lr] = bn.z; Bs[buf][lk + 3][lr] = bn.w;
            __syncthreads();
        }
    }

    float* out = g_Spart + ((size_t)((b * 9 + tile) * SPLIT + split) << 12);
#pragma unroll
    for (int i = 0; i < 4; i++) {
        float4 v = make_float4(acc[i][0], acc[i][1], acc[i][2], acc[i][3]);
        *(float4*)&out[(ty * 4 + i) * 64 + tx * 4] = v;
    }
}

// =====================================================================
// Kernel 2: deterministic split reduction. grid (36), 256 threads.
// =====================================================================
__global__ __launch_bounds__(256) void gram_reduce() {
    const int blk = blockIdx.x;
    const int b = blk / 9, tile = blk % 9;
    const int ti = tile / 3, tj = tile % 3;
    const float* base = g_Spart + ((size_t)(b * 9 + tile) * SPLIT << 12);
    for (int idx = threadIdx.x; idx < 4096; idx += 256) {
        float s = 0.f;
#pragma unroll
        for (int sp = 0; sp < SPLIT; sp++) s += base[(sp << 12) + idx];
        const int i = idx >> 6, j = idx & 63;
        g_S[b * CCH * CCH + (ti * 64 + i) * CCH + (tj * 64 + j)] = s;
    }
}

// =====================================================================
// Kernel 3: attention. grid (HEADS, BATCH), 192 threads, dynamic smem.
//  T1 = Wq_h @ S, T2 = Wk_h @ S  (24x192 each)
//  G[c,d] = <T1[c], Wk[d]>, nq/nk from diagonals, softmax -> g_attn
// =====================================================================
#define SD 193
#define ATTN_SMEM ((4 * 24 * SD + 576 + 48) * sizeof(float))

__global__ __launch_bounds__(192) void attn_kernel(const float* __restrict__ wqkv,
                                                   const float* __restrict__ temp) {
    const int h = blockIdx.x, b = blockIdx.y;
    extern __shared__ float sm[];
    float* Wq_s = sm;
    float* Wk_s = Wq_s + 24 * SD;
    float* T1s  = Wk_s + 24 * SD;
    float* T2s  = T1s + 24 * SD;
    float* Gs   = T2s + 24 * SD;
    float* nqv  = Gs + 576;
    float* nkv  = nqv + 24;

    const int tid = threadIdx.x;   // 0..191

    // load head rows of Wq, Wk
    for (int idx = tid; idx < 24 * 192; idx += 192) {
        const int c = idx / 192, a = idx % 192;
        Wq_s[c * SD + a] = wqkv[(h * CH + c) * CCH + a];
        Wk_s[c * SD + a] = wqkv[(CCH + h * CH + c) * CCH + a];
    }
    __syncthreads();

    // phase 1: T1[c,m], T2[c,m] for m = tid (uses S symmetry: S[a,m]=S[m,a])
    const int m = tid;
    float aq[CH], ak[CH];
#pragma unroll
    for (int c = 0; c < CH; c++) { aq[c] = 0.f; ak[c] = 0.f; }
    const float* Sb = g_S + b * CCH * CCH;
    for (int a = 0; a < CCH; a++) {
        const float s = Sb[a * CCH + m];
#pragma unroll
        for (int c = 0; c < CH; c++) {
            aq[c] = fmaf(Wq_s[c * SD + a], s, aq[c]);
            ak[c] = fmaf(Wk_s[c * SD + a], s, ak[c]);
        }
    }
#pragma unroll
    for (int c = 0; c < CH; c++) { T1s[c * SD + m] = aq[c]; T2s[c * SD + m] = ak[c]; }
    __syncthreads();

    // phase 2: G and norms
    for (int p = tid; p < 576; p += 192) {
        const int c = p / 24, d = p % 24;
        float g = 0.f;
        for (int mm = 0; mm < CCH; mm++)
            g = fmaf(T1s[c * SD + mm], Wk_s[d * SD + mm], g);
        Gs[p] = g;
    }
    if (tid < 24) {
        float s = 0.f;
        for (int mm = 0; mm < CCH; mm++)
            s = fmaf(T1s[tid * SD + mm], Wq_s[tid * SD + mm], s);
        nqv[tid] = fmaxf(sqrtf(s), 1e-12f);
    } else if (tid < 48) {
        const int c = tid - 24;
        float s = 0.f;
        for (int mm = 0; mm < CCH; mm++)
            s = fmaf(T2s[c * SD + mm], Wk_s[c * SD + mm], s);
        nkv[c] = fmaxf(sqrtf(s), 1e-12f);
    }
    __syncthreads();

    // phase 3: softmax rows
    if (tid < 24) {
        const int c = tid;
        const float tp = temp[h];
        float l[24];
        float mx = -1e30f;
#pragma unroll
        for (int d = 0; d < 24; d++) {
            l[d] = Gs[c * 24 + d] * tp / (nqv[c] * nkv[d]);
            mx = fmaxf(mx, l[d]);
        }
        float s = 0.f;
#pragma unroll
        for (int d = 0; d < 24; d++) { l[d] = expf(l[d] - mx); s += l[d]; }
        const float inv = 1.f / s;
        float* arow = g_attn + ((b * HEADS + h) * CH + c) * CH;
#pragma unroll
        for (int d = 0; d < 24; d++) arow[d] = l[d] * inv;
    }
}

// =====================================================================
// Kernel 4: M = W_out @ blockdiag(attn). grid(576), 256 threads.
// =====================================================================
__global__ __launch_bounds__(256) void m_kernel(const float* __restrict__ wout) {
    const int idx = blockIdx.x * 256 + threadIdx.x;
    const int b = idx / (CCH * CCH);
    const int r = idx % (CCH * CCH);
    const int o = r / CCH, j = r % CCH;
    const int h = j / CH, d = j % CH;
    const float* wrow = wout + o * CCH + h * CH;
    const float* acol = g_attn + ((b * HEADS + h) * CH) * CH + d;
    float s = 0.f;
#pragma unroll
    for (int c = 0; c < CH; c++) s = fmaf(wrow[c], acol[c * CH], s);
    g_M[idx] = s;
}

// =====================================================================
// Kernel 5: P = M @ W_v. grid (6,6,BATCH), 256 threads, 32x32 tiles.
// =====================================================================
__global__ __launch_bounds__(256) void p_kernel(const float* __restrict__ wqkv) {
    const int b = blockIdx.z;
    const int i0 = blockIdx.y * 32, j0 = blockIdx.x * 32;
    __shared__ float Ms[32][33], Ws[32][33];
    const int tid = threadIdx.x;
    const int tx = tid % 32, ty = tid / 32;   // ty 0..7
    float acc[4] = {0.f, 0.f, 0.f, 0.f};
    const float* Mb = g_M + b * CCH * CCH;
    for (int k0 = 0; k0 < CCH; k0 += 32) {
        const int r = tid / 32, kk = tid % 32;
#pragma unroll
        for (int rr = 0; rr < 32; rr += 8) {
            Ms[r + rr][kk] = Mb[(i0 + r + rr) * CCH + k0 + kk];
            Ws[r + rr][kk] = wqkv[(2 * CCH + k0 + r + rr) * CCH + j0 + kk];
        }
        __syncthreads();
#pragma unroll
        for (int k2 = 0; k2 < 32; k2++) {
            const float bv = Ws[k2][tx];
#pragma unroll
            for (int u = 0; u < 4; u++)
                acc[u] = fmaf(Ms[ty + 8 * u][k2], bv, acc[u]);
        }
        __syncthreads();
    }
#pragma unroll
    for (int u = 0; u < 4; u++)
        g_P[b * CCH * CCH + (i0 + ty + 8 * u) * CCH + j0 + tx] = acc[u];
}

// =====================================================================
// Kernel 6: Y = P @ X. grid (1024, 3, BATCH), 256 threads, 64x64 tiles.
// =====================================================================
__global__ __launch_bounds__(256) void y_kernel(const float* __restrict__ X,
                                                float* __restrict__ Y) {
    const int b  = blockIdx.z;
    const int i0 = blockIdx.y * 64;
    const int n0 = blockIdx.x * 64;
    const float* Pb = g_P + b * CCH * CCH;
    const float* Xb = X + (size_t)b * CCH * NPIX;
    float* Yb       = Y + (size_t)b * CCH * NPIX;

    __shared__ float As[2][16][68];
    __shared__ float Bs[2][16][68];

    const int t = threadIdx.x;
    const int alr = t >> 2, alk = (t & 3) * 4;
    const int bkr = t >> 4, bnq = (t & 15) * 4;
    const int tx = t & 15, ty = t >> 4;

    const float* ag = Pb + (i0 + alr) * CCH + alk;
    const float* bg = Xb + (size_t)bkr * NPIX + n0 + bnq;

    float4 av = *(const float4*)ag;
    float4 bv = *(const float4*)bg;
    As[0][alk + 0][alr] = av.x; As[0][alk + 1][alr] = av.y;
    As[0][alk + 2][alr] = av.z; As[0][alk + 3][alr] = av.w;
    *(float4*)&Bs[0][bkr][bnq] = bv;
    __syncthreads();

    float acc[4][4];
#pragma unroll
    for (int i = 0; i < 4; i++)
#pragma unroll
        for (int j = 0; j < 4; j++) acc[i][j] = 0.f;

    int buf = 0;
#pragma unroll 1
    for (int kt = 0; kt < 12; kt++) {
        float4 an, bn;
        if (kt < 11) {
            an = *(const float4*)(ag + (kt + 1) * 16);
            bn = *(const float4*)(bg + (size_t)(kt + 1) * 16 * NPIX);
        }
#pragma unroll
        for (int kk = 0; kk < 16; kk++) {
            float4 a  = *(const float4*)&As[buf][kk][ty * 4];
            float4 bb = *(const float4*)&Bs[buf][kk][tx * 4];
            float ar[4] = {a.x, a.y, a.z, a.w};
            float br[4] = {bb.x, bb.y, bb.z, bb.w};
#pragma unroll
            for (int i = 0; i < 4; i++)
#pragma unroll
                for (int j = 0; j < 4; j++)
                    acc[i][j] = fmaf(ar[i], br[j], acc[i][j]);
        }
        if (kt < 11) {
            buf ^= 1;
            As[buf][alk + 0][alr] = an.x; As[buf][alk + 1][alr] = an.y;
            As[buf][alk + 2][alr] = an.z; As[buf][alk + 3][alr] = an.w;
            *(float4*)&Bs[buf][bkr][bnq] = bn;
            __syncthreads();
        }
    }

#pragma unroll
    for (int i = 0; i < 4; i++) {
        float4 v = make_float4(acc[i][0], acc[i][1], acc[i][2], acc[i][3]);
        *(float4*)&Yb[(size_t)(i0 + ty * 4 + i) * NPIX + n0 + tx * 4] = v;
    }
}

// =====================================================================
// Launch
// =====================================================================
extern "C" void kernel_launch(void* const* d_in, const int* in_sizes, int n_in,
                              void* d_out, int out_size) {
    const float* x     = (const float*)d_in[0];
    const float* wqkv  = (const float*)d_in[1];
    const float* wout  = (const float*)d_in[2];
    const float* temp  = (const float*)d_in[3];
    float* y           = (float*)d_out;

    (void)in_sizes; (void)n_in; (void)out_size;

    static bool attr_set = false;
    if (!attr_set) {
        cudaFuncSetAttribute(attn_kernel, cudaFuncAttributeMaxDynamicSharedMemorySize,
                             (int)ATTN_SMEM);
        attr_set = true;
    }

    gram_partial<<<dim3(SPLIT, 9, BATCH), 256>>>(x);
    gram_reduce<<<36, 256>>>();
    attn_kernel<<<dim3(HEADS, BATCH), 192, ATTN_SMEM>>>(wqkv, temp);
    m_kernel<<<(BATCH * CCH * CCH) / 256, 256>>>(wout);
    p_kernel<<<dim3(6, 6, BATCH), 256>>>(wqkv);
    y_kernel<<<dim3(NPIX / 64, CCH / 64, BATCH), 256>>>(x, y);
}

// round 4
// speedup vs baseline: 2.0270x; 2.0270x over previous
#include <cuda_runtime.h>
#include <math.h>

// Problem constants
#define BATCH 4
#define CCH   192        // channels
#define NPIX  65536      // H*W
#define HEADS 8
#define CH    24         // channels per head (192/8)

// Gram split-K config
#define SPLIT 32
#define KCH   (NPIX / SPLIT)   // 2048

// ---------------- device scratch (static, no allocation) ----------------
__device__ float g_Spart[BATCH * 6 * SPLIT * 4096]; // per (b,tilepair,split) 64x64 partials
__device__ float g_S[BATCH * CCH * CCH];            // Gram X X^T per batch
__device__ float g_attn[BATCH * HEADS * CH * CH];   // softmaxed attention
__device__ float g_M[BATCH * CCH * CCH];            // W_out @ blockdiag(attn)
__device__ float g_P[BATCH * CCH * CCH];            // M @ W_v

// ---------------- tf32 helpers ----------------
__device__ __forceinline__ unsigned f2tf(float f) {
    unsigned u;
    asm("cvt.rna.tf32.f32 %0, %1;" : "=r"(u) : "f"(f));
    return u;
}

__device__ __forceinline__ void mma_tf32(float* d, const unsigned* a,
                                         unsigned b0, unsigned b1) {
    asm volatile(
        "mma.sync.aligned.m16n8k8.row.col.f32.tf32.tf32.f32 "
        "{%0,%1,%2,%3}, {%4,%5,%6,%7}, {%8,%9}, {%0,%1,%2,%3};"
        : "+f"(d[0]), "+f"(d[1]), "+f"(d[2]), "+f"(d[3])
        : "r"(a[0]), "r"(a[1]), "r"(a[2]), "r"(a[3]), "r"(b0), "r"(b1));
}

// tile-pair lookup: 6 upper-triangular 64x64 tiles of the 192x192 Gram
__device__ __forceinline__ void tile_pair(int tp, int& ti, int& tj) {
    ti = (tp < 3) ? 0 : ((tp < 5) ? 1 : 2);
    tj = (tp < 3) ? tp : ((tp < 5) ? tp - 2 : 2);
}

// =====================================================================
// Kernel 1: tf32 partial Gram. grid (6, SPLIT, BATCH), 128 threads.
// Block computes a 64x64 tile of S over a 2048-long K chunk.
// smem strides are 36 (== 4 mod 32) -> all fragment LDS conflict-free.
// =====================================================================
__global__ __launch_bounds__(128) void gram_tc(const float* __restrict__ X) {
    const int tp    = blockIdx.x;
    const int split = blockIdx.y;
    const int b     = blockIdx.z;
    int ti, tj; tile_pair(tp, ti, tj);

    const float* Xb = X + (size_t)b * CCH * NPIX;

    __shared__ unsigned As[64][36];
    __shared__ unsigned Bs[64][36];

    const int t    = threadIdx.x;
    const int lane = t & 31;
    const int wid  = t >> 5;
    const int g    = lane >> 2;   // 0..7
    const int tg   = lane & 3;    // 0..3
    const int wm   = (wid >> 1) * 32;   // warp m base (0/32)
    const int wn   = (wid & 1) * 32;    // warp n base (0/32)

    float acc[2][4][4];
#pragma unroll
    for (int mi = 0; mi < 2; mi++)
#pragma unroll
        for (int nj = 0; nj < 4; nj++)
#pragma unroll
            for (int u = 0; u < 4; u++) acc[mi][nj][u] = 0.f;

    const int kbase = split * KCH;

#pragma unroll 1
    for (int k0 = 0; k0 < KCH; k0 += 32) {
        __syncthreads();
        // load 64x32 A-tile and B-tile (fp32 -> tf32)
#pragma unroll
        for (int i = 0; i < 4; i++) {
            const int idx = t + i * 128;
            const int r = idx >> 3;
            const int c = (idx & 7) << 2;
            float4 a = *(const float4*)(Xb + (size_t)(ti * 64 + r) * NPIX + kbase + k0 + c);
            float4 v = *(const float4*)(Xb + (size_t)(tj * 64 + r) * NPIX + kbase + k0 + c);
            As[r][c + 0] = f2tf(a.x); As[r][c + 1] = f2tf(a.y);
            As[r][c + 2] = f2tf(a.z); As[r][c + 3] = f2tf(a.w);
            Bs[r][c + 0] = f2tf(v.x); Bs[r][c + 1] = f2tf(v.y);
            Bs[r][c + 2] = f2tf(v.z); Bs[r][c + 3] = f2tf(v.w);
        }
        __syncthreads();

#pragma unroll
        for (int kk = 0; kk < 32; kk += 8) {
            unsigned af[2][4], bf[4][2];
#pragma unroll
            for (int mi = 0; mi < 2; mi++) {
                const int m = wm + mi * 16;
                af[mi][0] = As[m + g][kk + tg];
                af[mi][1] = As[m + g + 8][kk + tg];
                af[mi][2] = As[m + g][kk + tg + 4];
                af[mi][3] = As[m + g + 8][kk + tg + 4];
            }
#pragma unroll
            for (int nj = 0; nj < 4; nj++) {
                const int n = wn + nj * 8;
                bf[nj][0] = Bs[n + g][kk + tg];
                bf[nj][1] = Bs[n + g][kk + tg + 4];
            }
#pragma unroll
            for (int mi = 0; mi < 2; mi++)
#pragma unroll
                for (int nj = 0; nj < 4; nj++)
                    mma_tf32(acc[mi][nj], af[mi], bf[nj][0], bf[nj][1]);
        }
    }

    // epilogue: 64x64 partial tile
    float* out = g_Spart + ((size_t)((b * 6 + tp) * SPLIT + split) << 12);
#pragma unroll
    for (int mi = 0; mi < 2; mi++)
#pragma unroll
        for (int nj = 0; nj < 4; nj++) {
            const int m0 = wm + mi * 16 + g;
            const int nc = wn + nj * 8 + 2 * tg;
            float2 lo = make_float2(acc[mi][nj][0], acc[mi][nj][1]);
            float2 hi = make_float2(acc[mi][nj][2], acc[mi][nj][3]);
            *(float2*)&out[m0 * 64 + nc]       = lo;
            *(float2*)&out[(m0 + 8) * 64 + nc] = hi;
        }
}

// =====================================================================
// Kernel 2: deterministic split reduction + symmetric mirror. grid(24).
// =====================================================================
__global__ __launch_bounds__(256) void gram_reduce6() {
    const int blk = blockIdx.x;
    const int b = blk / 6, tp = blk % 6;
    int ti, tj; tile_pair(tp, ti, tj);
    const float* base = g_Spart + ((size_t)(b * 6 + tp) * SPLIT << 12);
    for (int idx = threadIdx.x; idx < 4096; idx += 256) {
        float s = 0.f;
#pragma unroll
        for (int sp = 0; sp < SPLIT; sp++) s += base[(sp << 12) + idx];
        const int i = idx >> 6, j = idx & 63;
        g_S[b * CCH * CCH + (ti * 64 + i) * CCH + (tj * 64 + j)] = s;
        if (ti != tj)
            g_S[b * CCH * CCH + (tj * 64 + j) * CCH + (ti * 64 + i)] = s;
    }
}

// =====================================================================
// Kernel 3: attention. grid (HEADS, BATCH), 192 threads, dynamic smem.
// =====================================================================
#define SD 193
#define ATTN_SMEM ((4 * 24 * SD + 576 + 48) * sizeof(float))

__global__ __launch_bounds__(192) void attn_kernel(const float* __restrict__ wqkv,
                                                   const float* __restrict__ temp) {
    const int h = blockIdx.x, b = blockIdx.y;
    extern __shared__ float sm[];
    float* Wq_s = sm;
    float* Wk_s = Wq_s + 24 * SD;
    float* T1s  = Wk_s + 24 * SD;
    float* T2s  = T1s + 24 * SD;
    float* Gs   = T2s + 24 * SD;
    float* nqv  = Gs + 576;
    float* nkv  = nqv + 24;

    const int tid = threadIdx.x;

    for (int idx = tid; idx < 24 * 192; idx += 192) {
        const int c = idx / 192, a = idx % 192;
        Wq_s[c * SD + a] = wqkv[(h * CH + c) * CCH + a];
        Wk_s[c * SD + a] = wqkv[(CCH + h * CH + c) * CCH + a];
    }
    __syncthreads();

    const int m = tid;
    float aq[CH], ak[CH];
#pragma unroll
    for (int c = 0; c < CH; c++) { aq[c] = 0.f; ak[c] = 0.f; }
    const float* Sb = g_S + b * CCH * CCH;
    for (int a = 0; a < CCH; a++) {
        const float s = Sb[a * CCH + m];
#pragma unroll
        for (int c = 0; c < CH; c++) {
            aq[c] = fmaf(Wq_s[c * SD + a], s, aq[c]);
            ak[c] = fmaf(Wk_s[c * SD + a], s, ak[c]);
        }
    }
#pragma unroll
    for (int c = 0; c < CH; c++) { T1s[c * SD + m] = aq[c]; T2s[c * SD + m] = ak[c]; }
    __syncthreads();

    for (int p = tid; p < 576; p += 192) {
        const int c = p / 24, d = p % 24;
        float gg = 0.f;
        for (int mm = 0; mm < CCH; mm++)
            gg = fmaf(T1s[c * SD + mm], Wk_s[d * SD + mm], gg);
        Gs[p] = gg;
    }
    if (tid < 24) {
        float s = 0.f;
        for (int mm = 0; mm < CCH; mm++)
            s = fmaf(T1s[tid * SD + mm], Wq_s[tid * SD + mm], s);
        nqv[tid] = fmaxf(sqrtf(s), 1e-12f);
    } else if (tid < 48) {
        const int c = tid - 24;
        float s = 0.f;
        for (int mm = 0; mm < CCH; mm++)
            s = fmaf(T2s[c * SD + mm], Wk_s[c * SD + mm], s);
        nkv[c] = fmaxf(sqrtf(s), 1e-12f);
    }
    __syncthreads();

    if (tid < 24) {
        const int c = tid;
        const float tpv = temp[h];
        float l[24];
        float mx = -1e30f;
#pragma unroll
        for (int d = 0; d < 24; d++) {
            l[d] = Gs[c * 24 + d] * tpv / (nqv[c] * nkv[d]);
            mx = fmaxf(mx, l[d]);
        }
        float s = 0.f;
#pragma unroll
        for (int d = 0; d < 24; d++) { l[d] = expf(l[d] - mx); s += l[d]; }
        const float inv = 1.f / s;
        float* arow = g_attn + ((b * HEADS + h) * CH + c) * CH;
#pragma unroll
        for (int d = 0; d < 24; d++) arow[d] = l[d] * inv;
    }
}

// =====================================================================
// Kernel 4: M = W_out @ blockdiag(attn). grid(576), 256 threads.
// =====================================================================
__global__ __launch_bounds__(256) void m_kernel(const float* __restrict__ wout) {
    const int idx = blockIdx.x * 256 + threadIdx.x;
    const int b = idx / (CCH * CCH);
    const int r = idx % (CCH * CCH);
    const int o = r / CCH, j = r % CCH;
    const int h = j / CH, d = j % CH;
    const float* wrow = wout + o * CCH + h * CH;
    const float* acol = g_attn + ((b * HEADS + h) * CH) * CH + d;
    float s = 0.f;
#pragma unroll
    for (int c = 0; c < CH; c++) s = fmaf(wrow[c], acol[c * CH], s);
    g_M[idx] = s;
}

// =====================================================================
// Kernel 5: P = M @ W_v. grid (6,6,BATCH), 256 threads, 32x32 tiles.
// =====================================================================
__global__ __launch_bounds__(256) void p_kernel(const float* __restrict__ wqkv) {
    const int b = blockIdx.z;
    const int i0 = blockIdx.y * 32, j0 = blockIdx.x * 32;
    __shared__ float Ms[32][33], Ws[32][33];
    const int tid = threadIdx.x;
    const int tx = tid % 32, ty = tid / 32;
    float acc[4] = {0.f, 0.f, 0.f, 0.f};
    const float* Mb = g_M + b * CCH * CCH;
    for (int k0 = 0; k0 < CCH; k0 += 32) {
        const int r = tid / 32, kk = tid % 32;
#pragma unroll
        for (int rr = 0; rr < 32; rr += 8) {
            Ms[r + rr][kk] = Mb[(i0 + r + rr) * CCH + k0 + kk];
            Ws[r + rr][kk] = wqkv[(2 * CCH + k0 + r + rr) * CCH + j0 + kk];
        }
        __syncthreads();
#pragma unroll
        for (int k2 = 0; k2 < 32; k2++) {
            const float bv = Ws[k2][tx];
#pragma unroll
            for (int u = 0; u < 4; u++)
                acc[u] = fmaf(Ms[ty + 8 * u][k2], bv, acc[u]);
        }
        __syncthreads();
    }
#pragma unroll
    for (int u = 0; u < 4; u++)
        g_P[b * CCH * CCH + (i0 + ty + 8 * u) * CCH + j0 + tx] = acc[u];
}

// =====================================================================
// Kernel 6: tf32 Y = P @ X. grid (3, 1024, BATCH), 128 threads.
// Computes the OUTPUT TILE TRANSPOSED: Out[n][m] = sum_k X[k][n] * P[m][k]
// -> no smem transposes needed anywhere; strides 68/100 (== 4 mod 32)
//    keep every fragment LDS conflict-free.
// =====================================================================
__global__ __launch_bounds__(128) void y_tc(const float* __restrict__ X,
                                            float* __restrict__ Y) {
    const int b  = blockIdx.z;
    const int i0 = blockIdx.x * 64;   // m (output channel) base
    const int n0 = blockIdx.y * 64;   // pixel base

    __shared__ unsigned Ps[64][100];  // 64 m-rows x 96 k (half of K) + pad
    __shared__ unsigned Xs[32][68];   // 32 k-rows x 64 n + pad

    const float* Pb = g_P + b * CCH * CCH;
    const float* Xb = X + (size_t)b * CCH * NPIX;
    float* Yb       = Y + (size_t)b * CCH * NPIX;

    const int t    = threadIdx.x;
    const int lane = t & 31;
    const int wid  = t >> 5;
    const int g    = lane >> 2;
    const int tg   = lane & 3;
    const int wn_  = (wid >> 1) * 32;  // output-row (n) base of this warp
    const int wm_  = (wid & 1) * 32;   // output-col (m) base of this warp

    float acc[2][4][4];
#pragma unroll
    for (int ni = 0; ni < 2; ni++)
#pragma unroll
        for (int mj = 0; mj < 4; mj++)
#pragma unroll
            for (int u = 0; u < 4; u++) acc[ni][mj][u] = 0.f;

#pragma unroll 1
    for (int kh = 0; kh < CCH; kh += 96) {
#pragma unroll 1
        for (int k0 = 0; k0 < 96; k0 += 32) {
            __syncthreads();
            if (k0 == 0) {
                // load P half: 64 x 96 (fp32 -> tf32)
#pragma unroll
                for (int i = 0; i < 12; i++) {
                    const int idx = t + i * 128;
                    const int r = idx / 24;
                    const int c = (idx % 24) * 4;
                    float4 p = *(const float4*)(Pb + (i0 + r) * CCH + kh + c);
                    Ps[r][c + 0] = f2tf(p.x); Ps[r][c + 1] = f2tf(p.y);
                    Ps[r][c + 2] = f2tf(p.z); Ps[r][c + 3] = f2tf(p.w);
                }
            }
            // load X chunk: 32 k-rows x 64 n
#pragma unroll
            for (int i = 0; i < 4; i++) {
                const int idx = t + i * 128;
                const int r = idx >> 4;
                const int c = (idx & 15) << 2;
                float4 xv = *(const float4*)(Xb + (size_t)(kh + k0 + r) * NPIX + n0 + c);
                Xs[r][c + 0] = f2tf(xv.x); Xs[r][c + 1] = f2tf(xv.y);
                Xs[r][c + 2] = f2tf(xv.z); Xs[r][c + 3] = f2tf(xv.w);
            }
            __syncthreads();

#pragma unroll
            for (int kk = 0; kk < 32; kk += 8) {
                unsigned af[2][4], bf[4][2];
#pragma unroll
                for (int ni = 0; ni < 2; ni++) {
                    const int n = wn_ + ni * 16;
                    af[ni][0] = Xs[kk + tg][n + g];
                    af[ni][1] = Xs[kk + tg][n + g + 8];
                    af[ni][2] = Xs[kk + tg + 4][n + g];
                    af[ni][3] = Xs[kk + tg + 4][n + g + 8];
                }
#pragma unroll
                for (int mj = 0; mj < 4; mj++) {
                    const int mrow = wm_ + mj * 8 + g;
                    bf[mj][0] = Ps[mrow][k0 + kk + tg];
                    bf[mj][1] = Ps[mrow][k0 + kk + tg + 4];
                }
#pragma unroll
                for (int ni = 0; ni < 2; ni++)
#pragma unroll
                    for (int mj = 0; mj < 4; mj++)
                        mma_tf32(acc[ni][mj], af[ni], bf[mj][0], bf[mj][1]);
            }
        }
    }

    // epilogue: D[n'][m'] -> Y[m'][n'] (8-float runs along n = 32B sectors)
#pragma unroll
    for (int ni = 0; ni < 2; ni++)
#pragma unroll
        for (int mj = 0; mj < 4; mj++) {
            const int nrow = wn_ + ni * 16 + g;
            const int mcol = wm_ + mj * 8 + 2 * tg;
            float* y0 = Yb + (size_t)(i0 + mcol) * NPIX + n0;
            float* y1 = Yb + (size_t)(i0 + mcol + 1) * NPIX + n0;
            y0[nrow]     = acc[ni][mj][0];
            y1[nrow]     = acc[ni][mj][1];
            y0[nrow + 8] = acc[ni][mj][2];
            y1[nrow + 8] = acc[ni][mj][3];
        }
}

// =====================================================================
// Launch
// =====================================================================
extern "C" void kernel_launch(void* const* d_in, const int* in_sizes, int n_in,
                              void* d_out, int out_size) {
    const float* x     = (const float*)d_in[0];
    const float* wqkv  = (const float*)d_in[1];
    const float* wout  = (const float*)d_in[2];
    const float* temp  = (const float*)d_in[3];
    float* y           = (float*)d_out;

    (void)in_sizes; (void)n_in; (void)out_size;

    static bool attr_set = false;
    if (!attr_set) {
        cudaFuncSetAttribute(attn_kernel, cudaFuncAttributeMaxDynamicSharedMemorySize,
                             (int)ATTN_SMEM);
        attr_set = true;
    }

    gram_tc<<<dim3(6, SPLIT, BATCH), 128>>>(x);
    gram_reduce6<<<24, 256>>>();
    attn_kernel<<<dim3(HEADS, BATCH), 192, ATTN_SMEM>>>(wqkv, temp);
    m_kernel<<<(BATCH * CCH * CCH) / 256, 256>>>(wout);
    p_kernel<<<dim3(6, 6, BATCH), 256>>>(wqkv);
    y_tc<<<dim3(3, 1024, BATCH), 128>>>(x, y);
}

// round 5
// speedup vs baseline: 2.0342x; 1.0036x over previous
#include <cuda_runtime.h>
#include <math.h>

// Problem constants
#define BATCH 4
#define CCH   192        // channels
#define NPIX  65536      // H*W
#define HEADS 8
#define CH    24         // channels per head (192/8)

// Gram split-K config
#define SPLIT 32
#define KCH   (NPIX / SPLIT)   // 2048

// ---------------- device scratch (static, no allocation) ----------------
__device__ float g_Spart[BATCH * 6 * SPLIT * 4096]; // per (b,tilepair,split) 64x64 partials
__device__ float g_S[BATCH * CCH * CCH];            // Gram X X^T per batch
__device__ float g_attn[BATCH * HEADS * CH * CH];   // softmaxed attention
__device__ float g_M[BATCH * CCH * CCH];            // W_out @ blockdiag(attn)
__device__ float g_P[BATCH * CCH * CCH];            // M @ W_v

// ---------------- tf32 helpers ----------------
__device__ __forceinline__ unsigned f2tf(float f) {
    unsigned u;
    asm("cvt.rna.tf32.f32 %0, %1;" : "=r"(u) : "f"(f));
    return u;
}

__device__ __forceinline__ void mma_tf32(float* d, const unsigned* a,
                                         unsigned b0, unsigned b1) {
    asm volatile(
        "mma.sync.aligned.m16n8k8.row.col.f32.tf32.tf32.f32 "
        "{%0,%1,%2,%3}, {%4,%5,%6,%7}, {%8,%9}, {%0,%1,%2,%3};"
        : "+f"(d[0]), "+f"(d[1]), "+f"(d[2]), "+f"(d[3])
        : "r"(a[0]), "r"(a[1]), "r"(a[2]), "r"(a[3]), "r"(b0), "r"(b1));
}

// tile-pair lookup: 6 upper-triangular 64x64 tiles of the 192x192 Gram
__device__ __forceinline__ void tile_pair(int tp, int& ti, int& tj) {
    ti = (tp < 3) ? 0 : ((tp < 5) ? 1 : 2);
    tj = (tp < 3) ? tp : ((tp < 5) ? tp - 2 : 2);
}

// =====================================================================
// Kernel 1: tf32 partial Gram. grid (6, SPLIT, BATCH), 128 threads.
// Block computes a 64x64 tile of S over a 2048-long K chunk.
// smem strides are 36 (== 4 mod 32) -> all fragment LDS conflict-free.
// =====================================================================
__global__ __launch_bounds__(128) void gram_tc(const float* __restrict__ X) {
    const int tp    = blockIdx.x;
    const int split = blockIdx.y;
    const int b     = blockIdx.z;
    int ti, tj; tile_pair(tp, ti, tj);

    const float* Xb = X + (size_t)b * CCH * NPIX;

    __shared__ unsigned As[64][36];
    __shared__ unsigned Bs[64][36];

    const int t    = threadIdx.x;
    const int lane = t & 31;
    const int wid  = t >> 5;
    const int g    = lane >> 2;   // 0..7
    const int tg   = lane & 3;    // 0..3
    const int wm   = (wid >> 1) * 32;   // warp m base (0/32)
    const int wn   = (wid & 1) * 32;    // warp n base (0/32)

    float acc[2][4][4];
#pragma unroll
    for (int mi = 0; mi < 2; mi++)
#pragma unroll
        for (int nj = 0; nj < 4; nj++)
#pragma unroll
            for (int u = 0; u < 4; u++) acc[mi][nj][u] = 0.f;

    const int kbase = split * KCH;

#pragma unroll 1
    for (int k0 = 0; k0 < KCH; k0 += 32) {
        __syncthreads();
        // load 64x32 A-tile and B-tile (fp32 -> tf32)
#pragma unroll
        for (int i = 0; i < 4; i++) {
            const int idx = t + i * 128;
            const int r = idx >> 3;
            const int c = (idx & 7) << 2;
            float4 a = *(const float4*)(Xb + (size_t)(ti * 64 + r) * NPIX + kbase + k0 + c);
            float4 v = *(const float4*)(Xb + (size_t)(tj * 64 + r) * NPIX + kbase + k0 + c);
            As[r][c + 0] = f2tf(a.x); As[r][c + 1] = f2tf(a.y);
            As[r][c + 2] = f2tf(a.z); As[r][c + 3] = f2tf(a.w);
            Bs[r][c + 0] = f2tf(v.x); Bs[r][c + 1] = f2tf(v.y);
            Bs[r][c + 2] = f2tf(v.z); Bs[r][c + 3] = f2tf(v.w);
        }
        __syncthreads();

#pragma unroll
        for (int kk = 0; kk < 32; kk += 8) {
            unsigned af[2][4], bf[4][2];
#pragma unroll
            for (int mi = 0; mi < 2; mi++) {
                const int m = wm + mi * 16;
                af[mi][0] = As[m + g][kk + tg];
                af[mi][1] = As[m + g + 8][kk + tg];
                af[mi][2] = As[m + g][kk + tg + 4];
                af[mi][3] = As[m + g + 8][kk + tg + 4];
            }
#pragma unroll
            for (int nj = 0; nj < 4; nj++) {
                const int n = wn + nj * 8;
                bf[nj][0] = Bs[n + g][kk + tg];
                bf[nj][1] = Bs[n + g][kk + tg + 4];
            }
#pragma unroll
            for (int mi = 0; mi < 2; mi++)
#pragma unroll
                for (int nj = 0; nj < 4; nj++)
                    mma_tf32(acc[mi][nj], af[mi], bf[nj][0], bf[nj][1]);
        }
    }

    // epilogue: 64x64 partial tile
    float* out = g_Spart + ((size_t)((b * 6 + tp) * SPLIT + split) << 12);
#pragma unroll
    for (int mi = 0; mi < 2; mi++)
#pragma unroll
        for (int nj = 0; nj < 4; nj++) {
            const int m0 = wm + mi * 16 + g;
            const int nc = wn + nj * 8 + 2 * tg;
            float2 lo = make_float2(acc[mi][nj][0], acc[mi][nj][1]);
            float2 hi = make_float2(acc[mi][nj][2], acc[mi][nj][3]);
            *(float2*)&out[m0 * 64 + nc]       = lo;
            *(float2*)&out[(m0 + 8) * 64 + nc] = hi;
        }
}

// =====================================================================
// Kernel 2: deterministic split reduction + symmetric mirror. grid(24).
// =====================================================================
__global__ __launch_bounds__(256) void gram_reduce6() {
    const int blk = blockIdx.x;
    const int b = blk / 6, tp = blk % 6;
    int ti, tj; tile_pair(tp, ti, tj);
    const float* base = g_Spart + ((size_t)(b * 6 + tp) * SPLIT << 12);
    for (int idx = threadIdx.x; idx < 4096; idx += 256) {
        float s = 0.f;
#pragma unroll
        for (int sp = 0; sp < SPLIT; sp++) s += base[(sp << 12) + idx];
        const int i = idx >> 6, j = idx & 63;
        g_S[b * CCH * CCH + (ti * 64 + i) * CCH + (tj * 64 + j)] = s;
        if (ti != tj)
            g_S[b * CCH * CCH + (tj * 64 + j) * CCH + (ti * 64 + i)] = s;
    }
}

// =====================================================================
// Kernel 3: attention. grid (HEADS, BATCH), 192 threads, dynamic smem.
// =====================================================================
#define SD 193
#define ATTN_SMEM ((4 * 24 * SD + 576 + 48) * sizeof(float))

__global__ __launch_bounds__(192) void attn_kernel(const float* __restrict__ wqkv,
                                                   const float* __restrict__ temp) {
    const int h = blockIdx.x, b = blockIdx.y;
    extern __shared__ float sm[];
    float* Wq_s = sm;
    float* Wk_s = Wq_s + 24 * SD;
    float* T1s  = Wk_s + 24 * SD;
    float* T2s  = T1s + 24 * SD;
    float* Gs   = T2s + 24 * SD;
    float* nqv  = Gs + 576;
    float* nkv  = nqv + 24;

    const int tid = threadIdx.x;

    for (int idx = tid; idx < 24 * 192; idx += 192) {
        const int c = idx / 192, a = idx % 192;
        Wq_s[c * SD + a] = wqkv[(h * CH + c) * CCH + a];
        Wk_s[c * SD + a] = wqkv[(CCH + h * CH + c) * CCH + a];
    }
    __syncthreads();

    const int m = tid;
    float aq[CH], ak[CH];
#pragma unroll
    for (int c = 0; c < CH; c++) { aq[c] = 0.f; ak[c] = 0.f; }
    const float* Sb = g_S + b * CCH * CCH;
    for (int a = 0; a < CCH; a++) {
        const float s = Sb[a * CCH + m];
#pragma unroll
        for (int c = 0; c < CH; c++) {
            aq[c] = fmaf(Wq_s[c * SD + a], s, aq[c]);
            ak[c] = fmaf(Wk_s[c * SD + a], s, ak[c]);
        }
    }
#pragma unroll
    for (int c = 0; c < CH; c++) { T1s[c * SD + m] = aq[c]; T2s[c * SD + m] = ak[c]; }
    __syncthreads();

    for (int p = tid; p < 576; p += 192) {
        const int c = p / 24, d = p % 24;
        float gg = 0.f;
        for (int mm = 0; mm < CCH; mm++)
            gg = fmaf(T1s[c * SD + mm], Wk_s[d * SD + mm], gg);
        Gs[p] = gg;
    }
    if (tid < 24) {
        float s = 0.f;
        for (int mm = 0; mm < CCH; mm++)
            s = fmaf(T1s[tid * SD + mm], Wq_s[tid * SD + mm], s);
        nqv[tid] = fmaxf(sqrtf(s), 1e-12f);
    } else if (tid < 48) {
        const int c = tid - 24;
        float s = 0.f;
        for (int mm = 0; mm < CCH; mm++)
            s = fmaf(T2s[c * SD + mm], Wk_s[c * SD + mm], s);
        nkv[c] = fmaxf(sqrtf(s), 1e-12f);
    }
    __syncthreads();

    if (tid < 24) {
        const int c = tid;
        const float tpv = temp[h];
        float l[24];
        float mx = -1e30f;
#pragma unroll
        for (int d = 0; d < 24; d++) {
            l[d] = Gs[c * 24 + d] * tpv / (nqv[c] * nkv[d]);
            mx = fmaxf(mx, l[d]);
        }
        float s = 0.f;
#pragma unroll
        for (int d = 0; d < 24; d++) { l[d] = expf(l[d] - mx); s += l[d]; }
        const float inv = 1.f / s;
        float* arow = g_attn + ((b * HEADS + h) * CH + c) * CH;
#pragma unroll
        for (int d = 0; d < 24; d++) arow[d] = l[d] * inv;
    }
}

// =====================================================================
// Kernel 4: M = W_out @ blockdiag(attn). grid(576), 256 threads.
// =====================================================================
__global__ __launch_bounds__(256) void m_kernel(const float* __restrict__ wout) {
    const int idx = blockIdx.x * 256 + threadIdx.x;
    const int b = idx / (CCH * CCH);
    const int r = idx % (CCH * CCH);
    const int o = r / CCH, j = r % CCH;
    const int h = j / CH, d = j % CH;
    const float* wrow = wout + o * CCH + h * CH;
    const float* acol = g_attn + ((b * HEADS + h) * CH) * CH + d;
    float s = 0.f;
#pragma unroll
    for (int c = 0; c < CH; c++) s = fmaf(wrow[c], acol[c * CH], s);
    g_M[idx] = s;
}

// =====================================================================
// Kernel 5: P = M @ W_v. grid (6,6,BATCH), 256 threads, 32x32 tiles.
// =====================================================================
__global__ __launch_bounds__(256) void p_kernel(const float* __restrict__ wqkv) {
    const int b = blockIdx.z;
    const int i0 = blockIdx.y * 32, j0 = blockIdx.x * 32;
    __shared__ float Ms[32][33], Ws[32][33];
    const int tid = threadIdx.x;
    const int tx = tid % 32, ty = tid / 32;
    float acc[4] = {0.f, 0.f, 0.f, 0.f};
    const float* Mb = g_M + b * CCH * CCH;
    for (int k0 = 0; k0 < CCH; k0 += 32) {
        const int r = tid / 32, kk = tid % 32;
#pragma unroll
        for (int rr = 0; rr < 32; rr += 8) {
            Ms[r + rr][kk] = Mb[(i0 + r + rr) * CCH + k0 + kk];
            Ws[r + rr][kk] = wqkv[(2 * CCH + k0 + r + rr) * CCH + j0 + kk];
        }
        __syncthreads();
#pragma unroll
        for (int k2 = 0; k2 < 32; k2++) {
            const float bv = Ws[k2][tx];
#pragma unroll
            for (int u = 0; u < 4; u++)
                acc[u] = fmaf(Ms[ty + 8 * u][k2], bv, acc[u]);
        }
        __syncthreads();
    }
#pragma unroll
    for (int u = 0; u < 4; u++)
        g_P[b * CCH * CCH + (i0 + ty + 8 * u) * CCH + j0 + tx] = acc[u];
}

// =====================================================================
// Kernel 6: tf32 Y = P @ X. grid (3, 1024, BATCH), 128 threads.
// Computes the OUTPUT TILE TRANSPOSED: Out[n][m] = sum_k X[k][n] * P[m][k]
// -> no smem transposes needed anywhere; strides 68/100 (== 4 mod 32)
//    keep every fragment LDS conflict-free.
// =====================================================================
__global__ __launch_bounds__(128) void y_tc(const float* __restrict__ X,
                                            float* __restrict__ Y) {
    const int b  = blockIdx.z;
    const int i0 = blockIdx.x * 64;   // m (output channel) base
    const int n0 = blockIdx.y * 64;   // pixel base

    __shared__ unsigned Ps[64][100];  // 64 m-rows x 96 k (half of K) + pad
    __shared__ unsigned Xs[32][68];   // 32 k-rows x 64 n + pad

    const float* Pb = g_P + b * CCH * CCH;
    const float* Xb = X + (size_t)b * CCH * NPIX;
    float* Yb       = Y + (size_t)b * CCH * NPIX;

    const int t    = threadIdx.x;
    const int lane = t & 31;
    const int wid  = t >> 5;
    const int g    = lane >> 2;
    const int tg   = lane & 3;
    const int wn_  = (wid >> 1) * 32;  // output-row (n) base of this warp
    const int wm_  = (wid & 1) * 32;   // output-col (m) base of this warp

    float acc[2][4][4];
#pragma unroll
    for (int ni = 0; ni < 2; ni++)
#pragma unroll
        for (int mj = 0; mj < 4; mj++)
#pragma unroll
            for (int u = 0; u < 4; u++) acc[ni][mj][u] = 0.f;

#pragma unroll 1
    for (int kh = 0; kh < CCH; kh += 96) {
#pragma unroll 1
        for (int k0 = 0; k0 < 96; k0 += 32) {
            __syncthreads();
            if (k0 == 0) {
                // load P half: 64 x 96 (fp32 -> tf32)
#pragma unroll
                for (int i = 0; i < 12; i++) {
                    const int idx = t + i * 128;
                    const int r = idx / 24;
                    const int c = (idx % 24) * 4;
                    float4 p = *(const float4*)(Pb + (i0 + r) * CCH + kh + c);
                    Ps[r][c + 0] = f2tf(p.x); Ps[r][c + 1] = f2tf(p.y);
                    Ps[r][c + 2] = f2tf(p.z); Ps[r][c + 3] = f2tf(p.w);
                }
            }
            // load X chunk: 32 k-rows x 64 n
#pragma unroll
            for (int i = 0; i < 4; i++) {
                const int idx = t + i * 128;
                const int r = idx >> 4;
                const int c = (idx & 15) << 2;
                float4 xv = *(const float4*)(Xb + (size_t)(kh + k0 + r) * NPIX + n0 + c);
                Xs[r][c + 0] = f2tf(xv.x); Xs[r][c + 1] = f2tf(xv.y);
                Xs[r][c + 2] = f2tf(xv.z); Xs[r][c + 3] = f2tf(xv.w);
            }
            __syncthreads();

#pragma unroll
            for (int kk = 0; kk < 32; kk += 8) {
                unsigned af[2][4], bf[4][2];
#pragma unroll
                for (int ni = 0; ni < 2; ni++) {
                    const int n = wn_ + ni * 16;
                    af[ni][0] = Xs[kk + tg][n + g];
                    af[ni][1] = Xs[kk + tg][n + g + 8];
                    af[ni][2] = Xs[kk + tg + 4][n + g];
                    af[ni][3] = Xs[kk + tg + 4][n + g + 8];
                }
#pragma unroll
                for (int mj = 0; mj < 4; mj++) {
                    const int mrow = wm_ + mj * 8 + g;
                    bf[mj][0] = Ps[mrow][k0 + kk + tg];
                    bf[mj][1] = Ps[mrow][k0 + kk + tg + 4];
                }
#pragma unroll
                for (int ni = 0; ni < 2; ni++)
#pragma unroll
                    for (int mj = 0; mj < 4; mj++)
                        mma_tf32(acc[ni][mj], af[ni], bf[mj][0], bf[mj][1]);
            }
        }
    }

    // epilogue: D[n'][m'] -> Y[m'][n'] (8-float runs along n = 32B sectors)
#pragma unroll
    for (int ni = 0; ni < 2; ni++)
#pragma unroll
        for (int mj = 0; mj < 4; mj++) {
            const int nrow = wn_ + ni * 16 + g;
            const int mcol = wm_ + mj * 8 + 2 * tg;
            float* y0 = Yb + (size_t)(i0 + mcol) * NPIX + n0;
            float* y1 = Yb + (size_t)(i0 + mcol + 1) * NPIX + n0;
            y0[nrow]     = acc[ni][mj][0];
            y1[nrow]     = acc[ni][mj][1];
            y0[nrow + 8] = acc[ni][mj][2];
            y1[nrow + 8] = acc[ni][mj][3];
        }
}

// =====================================================================
// Launch
// =====================================================================
extern "C" void kernel_launch(void* const* d_in, const int* in_sizes, int n_in,
                              void* d_out, int out_size) {
    const float* x     = (const float*)d_in[0];
    const float* wqkv  = (const float*)d_in[1];
    const float* wout  = (const float*)d_in[2];
    const float* temp  = (const float*)d_in[3];
    float* y           = (float*)d_out;

    (void)in_sizes; (void)n_in; (void)out_size;

    static bool attr_set = false;
    if (!attr_set) {
        cudaFuncSetAttribute(attn_kernel, cudaFuncAttributeMaxDynamicSharedMemorySize,
                             (int)ATTN_SMEM);
        attr_set = true;
    }

    gram_tc<<<dim3(6, SPLIT, BATCH), 128>>>(x);
    gram_reduce6<<<24, 256>>>();
    attn_kernel<<<dim3(HEADS, BATCH), 192, ATTN_SMEM>>>(wqkv, temp);
    m_kernel<<<(BATCH * CCH * CCH) / 256, 256>>>(wout);
    p_kernel<<<dim3(6, 6, BATCH), 256>>>(wqkv);
    y_tc<<<dim3(3, 1024, BATCH), 128>>>(x, y);
}